// round 3
// baseline (speedup 1.0000x reference)
#include <cuda_runtime.h>
#include <cuda_bf16.h>

// SchNetClassifier — analytically collapsed + latency-optimized.
//   out[b] = base + sum_{m=1..511} ( cb + sum_d rbf_d(|r0 - rm|) * c_d )
//   base = Q_b + Q.e,  c_d = sum_f (Q_f x_f) Wc_w[f,d],  cb = sum_f (Q_f x_f) Wc_b[f]
//   x_g  = Wi_b[g] + sum_f e_f Wi_w[g,f]
//
// rbf via exact recurrence: rbf_{k+1} = rbf_k * R' * E_k with
//   forward  (u < 0.95): a = exp(-10 u^2),        R' = exp(2u - 0.1), idx = k
//   backward (u >= 0.95): a = exp(-10 (u-1.9)^2), R' = exp(3.7 - 2u), idx = 19-k
//   E_k = exp(-0.2 k).  Every intermediate equals the true rbf value (<= 1).
// Cuts MUFU work 21 -> 3 ops per neighbor and removes one __syncthreads.

#define FDIM 16
#define DDIM 20
#define NPTS 512
#define NT 256

__device__ __constant__ const float EKc[19] = {
    1.0f,          0.81873075f, 0.67032005f, 0.54881164f, 0.44932896f,
    0.36787944f,   0.30119421f, 0.24659696f, 0.20189652f, 0.16529889f,
    0.13533528f,   0.11080316f, 0.09071795f, 0.07427358f, 0.06081006f,
    0.04978707f,   0.04076220f, 0.03337327f, 0.02732372f };

__global__ __launch_bounds__(NT)
void schnet_kernel(const float* __restrict__ coords,
                   const float* __restrict__ atom_emb,
                   const float* __restrict__ Wc_w,
                   const float* __restrict__ Wc_b,
                   const float* __restrict__ Wi_w,
                   const float* __restrict__ Wi_b,
                   const float* __restrict__ Q_w,
                   const float* __restrict__ Q_b,
                   float* __restrict__ out) {
    __shared__ float c_sh[DDIM + 2];     // [0..19]=c_d, [20]=cb, [21]=base
    __shared__ float red[NT / 32];

    const int tid  = threadIdx.x;
    const int lane = tid & 31;
    const int wid  = tid >> 5;
    const int b    = blockIdx.x;

    // ------------- coordinate loads (all threads, front-batched) ----------
    const float* C = coords + (size_t)b * NPTS * 3;
    const float ox = C[0], oy = C[1], oz = C[2];
    const int m1 = tid, m2 = tid + NT;
    const float ax = C[m1*3+0], ay = C[m1*3+1], az = C[m1*3+2];
    const float bx = C[m2*3+0], by = C[m2*3+1], bz = C[m2*3+2];

    // ------------- warp 0: prelude (shuffle-based, no block barrier) ------
    if (wid == 0) {
        float e_r[FDIM], wi_r[FDIM], wc_r[FDIM];
        float bias = 0.f, q = 0.f, cv0 = 0.f;
        if (lane < FDIM) {
            #pragma unroll
            for (int f = 0; f < FDIM; f++) e_r[f]  = atom_emb[f];
            #pragma unroll
            for (int f = 0; f < FDIM; f++) wi_r[f] = Wi_w[lane * FDIM + f];
            bias = Wi_b[lane];
            q    = Q_w[lane];
        }
        if (lane < DDIM) {
            #pragma unroll
            for (int f = 0; f < FDIM; f++) wc_r[f] = Wc_w[f * DDIM + lane];
        } else if (lane == DDIM) {
            #pragma unroll
            for (int f = 0; f < FDIM; f++) wc_r[f] = Wc_b[f];
        } else if (lane == DDIM + 1) {
            #pragma unroll
            for (int f = 0; f < FDIM; f++) { wc_r[f] = Q_w[f]; e_r[f] = atom_emb[f]; }
            cv0 = Q_b[0];
        } else {
            #pragma unroll
            for (int f = 0; f < FDIM; f++) { wc_r[f] = 0.f; e_r[f] = 0.f; }
        }

        // y_f = Q_f * (Wi_b[f] + e . Wi_w[f,:])   (valid on lanes 0..15)
        float x = bias;
        #pragma unroll
        for (int f = 0; f < FDIM; f++) x = fmaf(e_r[f], wi_r[f], x);
        const float y = q * x;

        // lanes 0..19: c_d = sum_f y_f wc_r[f]; lane 20: cb; lane 21: base
        float cv = cv0;
        #pragma unroll
        for (int f = 0; f < FDIM; f++) {
            const float yf = __shfl_sync(0xFFFFFFFFu, y, f);
            const float sf = (lane == DDIM + 1) ? e_r[f] : yf;
            cv = fmaf(wc_r[f], sf, cv);
        }
        if (lane <= DDIM + 1) c_sh[lane] = cv;
    }

    // ------------- all threads: rbf vectors (overlaps warp0 prelude) ------
    float rb1[DDIM], rb2[DDIM];
    {
        const float dx = ax-ox, dy = ay-oy, dz = az-oz;
        const float u  = sqrtf(fmaf(dx,dx,fmaf(dy,dy,dz*dz)));
        const bool fwd = u < 0.95f;
        const float t0 = fwd ? u : (u - 1.9f);
        rb1[0] = __expf(-10.f * t0 * t0);
        const float Rp = __expf(fwd ? (2.f*u - 0.1f) : (3.7f - 2.f*u));
        #pragma unroll
        for (int k = 0; k < DDIM-1; k++) rb1[k+1] = rb1[k] * (Rp * EKc[k]);
    }
    int base2;
    {
        const float dx = bx-ox, dy = by-oy, dz = bz-oz;
        const float u  = sqrtf(fmaf(dx,dx,fmaf(dy,dy,dz*dz)));
        const bool fwd = u < 0.95f;
        const float t0 = fwd ? u : (u - 1.9f);
        rb2[0] = __expf(-10.f * t0 * t0);
        const float Rp = __expf(fwd ? (2.f*u - 0.1f) : (3.7f - 2.f*u));
        #pragma unroll
        for (int k = 0; k < DDIM-1; k++) rb2[k+1] = rb2[k] * (Rp * EKc[k]);
        base2 = fwd ? 0 : (DDIM - 1);
    }
    // direction index base/step for pair 1 (recompute flag cheaply)
    int base1;
    {
        const float dx = ax-ox, dy = ay-oy, dz = az-oz;
        const float u2 = fmaf(dx,dx,fmaf(dy,dy,dz*dz));
        base1 = (u2 < 0.9025f) ? 0 : (DDIM - 1);   // u < 0.95  <=>  u^2 < 0.9025
    }
    const int step1 = base1 ? -1 : 1;
    const int step2 = base2 ? -1 : 1;

    __syncthreads();

    // ------------- fold rbf with c_d -------------------------------------
    const float cb = c_sh[DDIM];
    float s1 = cb, s2 = cb;
    #pragma unroll
    for (int k = 0; k < DDIM; k++) {
        s1 = fmaf(rb1[k], c_sh[base1 + step1 * k], s1);
        s2 = fmaf(rb2[k], c_sh[base2 + step2 * k], s2);
    }
    float acc = ((tid == 0) ? 0.f : s1) + s2;   // m=0 excluded (diagonal)

    // ------------- reduction: 8 warps ------------------------------------
    #pragma unroll
    for (int off = 16; off > 0; off >>= 1)
        acc += __shfl_xor_sync(0xFFFFFFFFu, acc, off);
    if (lane == 0) red[wid] = acc;
    __syncthreads();
    if (tid < NT / 32) {
        float v = red[tid];
        #pragma unroll
        for (int off = NT / 64; off > 0; off >>= 1)
            v += __shfl_xor_sync(0xFFu, v, off);
        if (tid == 0) out[b] = c_sh[DDIM + 1] + v;
    }
}

extern "C" void kernel_launch(void* const* d_in, const int* in_sizes, int n_in,
                              void* d_out, int out_size) {
    const float* coords   = (const float*)d_in[0];
    const float* atom_emb = (const float*)d_in[1];
    const float* Wc_w     = (const float*)d_in[2];
    const float* Wc_b     = (const float*)d_in[3];
    const float* Wi_w     = (const float*)d_in[4];
    const float* Wi_b     = (const float*)d_in[5];
    const float* Q_w      = (const float*)d_in[6];
    const float* Q_b      = (const float*)d_in[7];
    float* out = (float*)d_out;

    const int B = in_sizes[0] / (NPTS * 3);
    schnet_kernel<<<B, NT>>>(coords, atom_emb, Wc_w, Wc_b,
                             Wi_w, Wi_b, Q_w, Q_b, out);
}

// round 4
// speedup vs baseline: 1.0385x; 1.0385x over previous
#include <cuda_runtime.h>
#include <cuda_bf16.h>

// SchNetClassifier — analytically collapsed.
//   out[b] = base + sum_{m=1..511} ( cb + sum_d rbf_d(|r0 - rm|) * c_d )
//   base = Q_b + Q.e,  c_d = sum_f (Q_f x_f) Wc_w[f,d],  cb = sum_f (Q_f x_f) Wc_b[f]
//   x_g  = Wi_b[g] + sum_f e_f Wi_w[g,f]
//
// rbf via exact forward recurrence: rbf_{k+1} = rbf_k * Rp * E_k,
//   rbf_0 = exp(-10 u^2), Rp = exp(2u - 0.1), E_k = exp(-0.2k).
// Underflow (u > 3.17) truncates terms <= 1e-7 — 100x below tolerance.
//
// Warp 0 is a dedicated prelude warp (weights -> c_d); warps 1..8 own the
// 512 neighbors (2 each). One block barrier total before the reduction.

#define FDIM 16
#define DDIM 20
#define NPTS 512
#define NT 288            // 9 warps
#define NW (NT / 32)

__global__ __launch_bounds__(NT)
void schnet_kernel(const float* __restrict__ coords,
                   const float* __restrict__ atom_emb,
                   const float* __restrict__ Wc_w,
                   const float* __restrict__ Wc_b,
                   const float* __restrict__ Wi_w,
                   const float* __restrict__ Wi_b,
                   const float* __restrict__ Q_w,
                   const float* __restrict__ Q_b,
                   float* __restrict__ out) {
    __shared__ float c_sh[DDIM + 2];     // [0..19]=c_d, [20]=cb, [21]=base
    __shared__ float red[NW];

    const int tid  = threadIdx.x;
    const int lane = tid & 31;
    const int wid  = tid >> 5;
    const int b    = blockIdx.x;

    const float* C = coords + (size_t)b * NPTS * 3;

    // E_k = exp(-0.2 k) as compile-time constants (become FFMA immediates)
    constexpr float EK[DDIM - 1] = {
        1.0f,        0.81873075f, 0.67032005f, 0.54881164f, 0.44932896f,
        0.36787944f, 0.30119421f, 0.24659696f, 0.20189652f, 0.16529889f,
        0.13533528f, 0.11080316f, 0.09071795f, 0.07427358f, 0.06081006f,
        0.04978707f, 0.04076220f, 0.03337327f, 0.02732372f };

    float rb1[DDIM], rb2[DDIM];

    if (wid == 0) {
        // ---------------- dedicated prelude warp --------------------------
        float e_r[FDIM], wi_r[FDIM], wc_r[FDIM];
        float bias = 0.f, q = 0.f, cv0 = 0.f;
        if (lane < FDIM) {
            #pragma unroll
            for (int f = 0; f < FDIM; f++) e_r[f]  = atom_emb[f];
            #pragma unroll
            for (int f = 0; f < FDIM; f++) wi_r[f] = Wi_w[lane * FDIM + f];
            bias = Wi_b[lane];
            q    = Q_w[lane];
        }
        if (lane < DDIM) {
            #pragma unroll
            for (int f = 0; f < FDIM; f++) wc_r[f] = Wc_w[f * DDIM + lane];
        } else if (lane == DDIM) {
            #pragma unroll
            for (int f = 0; f < FDIM; f++) wc_r[f] = Wc_b[f];
        } else if (lane == DDIM + 1) {
            #pragma unroll
            for (int f = 0; f < FDIM; f++) { wc_r[f] = Q_w[f]; e_r[f] = atom_emb[f]; }
            cv0 = Q_b[0];
        } else {
            #pragma unroll
            for (int f = 0; f < FDIM; f++) { wc_r[f] = 0.f; e_r[f] = 0.f; }
        }

        // y_f = Q_f * (Wi_b[f] + e . Wi_w[f,:])   (valid on lanes 0..15)
        float x = bias;
        #pragma unroll
        for (int f = 0; f < FDIM; f++) x = fmaf(e_r[f], wi_r[f], x);
        const float y = q * x;

        // lanes 0..19: c_d ; lane 20: cb ; lane 21: base = Q_b + Q.e
        float cv = cv0;
        #pragma unroll
        for (int f = 0; f < FDIM; f++) {
            const float yf = __shfl_sync(0xFFFFFFFFu, y, f);
            const float sf = (lane == DDIM + 1) ? e_r[f] : yf;
            cv = fmaf(wc_r[f], sf, cv);
        }
        if (lane <= DDIM + 1) c_sh[lane] = cv;
    } else {
        // ---------------- neighbor warps: rbf precompute ------------------
        const int idx = tid - 32;            // 0..255
        const float ox = C[0], oy = C[1], oz = C[2];
        const int m1 = idx, m2 = idx + 256;
        const float ax = C[m1*3+0], ay = C[m1*3+1], az = C[m1*3+2];
        const float bx = C[m2*3+0], by = C[m2*3+1], bz = C[m2*3+2];

        {
            const float dx = ax-ox, dy = ay-oy, dz = az-oz;
            const float u  = sqrtf(fmaf(dx,dx,fmaf(dy,dy,dz*dz)));
            rb1[0] = __expf(-10.f * u * u);
            const float Rp = __expf(2.f*u - 0.1f);
            #pragma unroll
            for (int k = 0; k < DDIM-1; k++) rb1[k+1] = rb1[k] * (Rp * EK[k]);
        }
        {
            const float dx = bx-ox, dy = by-oy, dz = bz-oz;
            const float u  = sqrtf(fmaf(dx,dx,fmaf(dy,dy,dz*dz)));
            rb2[0] = __expf(-10.f * u * u);
            const float Rp = __expf(2.f*u - 0.1f);
            #pragma unroll
            for (int k = 0; k < DDIM-1; k++) rb2[k+1] = rb2[k] * (Rp * EK[k]);
        }
    }

    __syncthreads();

    // ---------------- fold rbf with c_d (uniform LDS -> broadcast) --------
    float acc = 0.f;
    if (wid != 0) {
        const float cb = c_sh[DDIM];
        float s1 = cb, s2 = cb;
        #pragma unroll
        for (int k = 0; k < DDIM; k++) {
            const float ck = c_sh[k];
            s1 = fmaf(rb1[k], ck, s1);
            s2 = fmaf(rb2[k], ck, s2);
        }
        acc = ((tid == 32) ? 0.f : s1) + s2;   // m=0 excluded (diagonal)
    }

    // ---------------- reduction: 9 warps ----------------------------------
    #pragma unroll
    for (int off = 16; off > 0; off >>= 1)
        acc += __shfl_xor_sync(0xFFFFFFFFu, acc, off);
    if (lane == 0) red[wid] = acc;
    __syncthreads();
    if (tid < 16) {
        float v = (tid < NW) ? red[tid] : 0.f;
        #pragma unroll
        for (int off = 8; off > 0; off >>= 1)
            v += __shfl_xor_sync(0xFFFFu, v, off);
        if (tid == 0) out[b] = c_sh[DDIM + 1] + v;
    }
}

extern "C" void kernel_launch(void* const* d_in, const int* in_sizes, int n_in,
                              void* d_out, int out_size) {
    const float* coords   = (const float*)d_in[0];
    const float* atom_emb = (const float*)d_in[1];
    const float* Wc_w     = (const float*)d_in[2];
    const float* Wc_b     = (const float*)d_in[3];
    const float* Wi_w     = (const float*)d_in[4];
    const float* Wi_b     = (const float*)d_in[5];
    const float* Q_w      = (const float*)d_in[6];
    const float* Q_b      = (const float*)d_in[7];
    float* out = (float*)d_out;

    const int B = in_sizes[0] / (NPTS * 3);
    schnet_kernel<<<B, NT>>>(coords, atom_emb, Wc_w, Wc_b,
                             Wi_w, Wi_b, Q_w, Q_b, out);
}